// round 6
// baseline (speedup 1.0000x reference)
#include <cuda_runtime.h>
#include <cstdint>

#define MROWS 8192
#define NCOLS 8192
#define DIN   128
#define DH    256
#define TOPK  512

// ---------- MLP tiling ----------
#define BM 128
#define BN 128
#define BK 16
#define NTHREADS 256

// ---------- sim tiling (mma.sync tf32 + cp.async.bulk) ----------
#define TM 256
#define TN 128
#define NSTAGE 48            // 3 terms x 16 stages (K_eff = 768)
#define NSTB 4               // pipeline depth (3 in flight)
#define A_RSTRIDE 264        // 256 + 8 pad (floats)
#define B_RSTRIDE 136        // 128 + 8 pad
#define A_STG (16 * A_RSTRIDE)   // 4224 floats
#define B_STG (16 * B_RSTRIDE)   // 2176 floats
#define B_BASE (NSTB * A_STG)    // 16896
#define SIM_SMEM ((B_BASE + NSTB * B_STG) * 4)   // 102400 B
#define STAGE_BYTES (16 * 1024 + 16 * 512)       // 24576

#define NBX (NCOLS / TN)     // 64
#define NBY (MROWS / TM)     // 32
#define NBLOCKS (NBX * NBY)  // 2048

#define CAND_BUF  32768
#define CAND_SORT 4096

// ---------------- scratch (device globals; no allocation allowed) ----------
__device__ __align__(128) float g_hid0[MROWS * DH];
__device__ __align__(128) float g_hid1[NCOLS * DH];
// K-major: [k][sample]; k 0..255 = tf32 hi, k 256..511 = exact fp32 residual
__device__ __align__(128) float g_a2t[512 * MROWS];
__device__ __align__(128) float g_b2t[512 * NCOLS];
__device__ float g_blockmax[NBLOCKS];
__device__ float g_thresh;
__device__ unsigned int g_ccount;
__device__ unsigned long long g_cand[CAND_BUF];

// monotone float -> uint key
__device__ __forceinline__ unsigned int fkey(float f) {
    unsigned int u = __float_as_uint(f);
    return (u & 0x80000000u) ? ~u : (u | 0x80000000u);
}

__device__ __forceinline__ unsigned int tf32_bits(float x) {
    unsigned int u;
    asm("cvt.rna.tf32.f32 %0, %1;" : "=r"(u) : "f"(x));
    return u;
}

__device__ __forceinline__ void mbar_wait(uint32_t a, uint32_t phase) {
    uint32_t done;
    asm volatile(
        "{\n\t.reg .pred p;\n\t"
        "mbarrier.try_wait.parity.acquire.cta.shared::cta.b64 p, [%1], %2;\n\t"
        "selp.b32 %0, 1, 0, p;\n\t}"
        : "=r"(done) : "r"(a), "r"(phase) : "memory");
    if (!done) {
        asm volatile(
            "{\n\t.reg .pred P1;\n\t"
            "WL_%=:\n\t"
            "mbarrier.try_wait.parity.acquire.cta.shared::cta.b64 P1, [%0], %1, 0x989680;\n\t"
            "@P1 bra.uni WD_%=;\n\t"
            "bra.uni WL_%=;\n\t"
            "WD_%=:\n\t}"
            :: "r"(a), "r"(phase) : "memory");
    }
}

__device__ __forceinline__ void bulk_cp(uint32_t dst, const void* src,
                                        uint32_t bytes, uint32_t mbar) {
    asm volatile(
        "cp.async.bulk.shared::cta.global.mbarrier::complete_tx::bytes [%0], [%1], %2, [%3];"
        :: "r"(dst), "l"(src), "r"(bytes), "r"(mbar) : "memory");
}

// ---------------- MLP GEMM: O = act(A @ W + b), N = DH = 256 ---------------
__global__ __launch_bounds__(NTHREADS, 2)
void mlp_gemm_kernel(const float* __restrict__ in0, const float* __restrict__ in1,
                     const float* __restrict__ Wd0, const float* __restrict__ Wd1,
                     const float* __restrict__ bd0, const float* __restrict__ bd1,
                     int layer)
{
    const int z = blockIdx.z;
    const float* A;
    float* O;
    int K, relu;
    if (layer == 0) {
        A = z ? in1 : in0;
        O = z ? g_hid1 : g_hid0;
        K = DIN; relu = 1;
    } else {
        A = z ? g_hid1 : g_hid0;
        O = z ? g_b2t : g_a2t;
        K = DH; relu = 0;
    }
    const float* W = z ? Wd1 : Wd0;
    const float* bias = z ? bd1 : bd0;

    __shared__ float As[BK][BM];
    __shared__ float Bs[BK][BN];

    const int tid = threadIdx.x;
    const int tx = tid & 15, ty = tid >> 4;
    const int r0 = blockIdx.y * BM;
    const int c0 = blockIdx.x * BN;

    float acc[8][8];
#pragma unroll
    for (int i = 0; i < 8; i++)
#pragma unroll
        for (int j = 0; j < 8; j++) acc[i][j] = 0.0f;

    for (int k0 = 0; k0 < K; k0 += BK) {
#pragma unroll
        for (int i = 0; i < 2; i++) {
            int f = tid * 2 + i;
            int row = f >> 2;
            int kq = (f & 3) << 2;
            float4 v = *(const float4*)(A + (size_t)(r0 + row) * K + k0 + kq);
            As[kq + 0][row] = v.x; As[kq + 1][row] = v.y;
            As[kq + 2][row] = v.z; As[kq + 3][row] = v.w;
        }
#pragma unroll
        for (int i = 0; i < 2; i++) {
            int f = tid * 2 + i;
            int kk = f >> 5;
            int nq = (f & 31) << 2;
            *(float4*)&Bs[kk][nq] =
                *(const float4*)(W + (size_t)(k0 + kk) * DH + c0 + nq);
        }
        __syncthreads();
#pragma unroll
        for (int kk = 0; kk < BK; kk++) {
            float a[8], b[8];
            *(float4*)&a[0] = *(float4*)&As[kk][ty * 8];
            *(float4*)&a[4] = *(float4*)&As[kk][ty * 8 + 4];
            *(float4*)&b[0] = *(float4*)&Bs[kk][tx * 8];
            *(float4*)&b[4] = *(float4*)&Bs[kk][tx * 8 + 4];
#pragma unroll
            for (int i = 0; i < 8; i++)
#pragma unroll
                for (int j = 0; j < 8; j++)
                    acc[i][j] = fmaf(a[i], b[j], acc[i][j]);
        }
        __syncthreads();
    }

    float bv[8];
    *(float4*)&bv[0] = *(const float4*)(bias + c0 + tx * 8);
    *(float4*)&bv[4] = *(const float4*)(bias + c0 + tx * 8 + 4);

    if (relu) {
#pragma unroll
        for (int i = 0; i < 8; i++) {
            int row = r0 + ty * 8 + i;
            float f[8];
#pragma unroll
            for (int j = 0; j < 8; j++) f[j] = fmaxf(acc[i][j] + bv[j], 0.0f);
            *(float4*)(O + (size_t)row * DH + c0 + tx * 8) = *(float4*)&f[0];
            *(float4*)(O + (size_t)row * DH + c0 + tx * 8 + 4) = *(float4*)&f[4];
        }
    } else {
        // K-major store with exact hi/lo split: O[k][sample]
#pragma unroll
        for (int j = 0; j < 8; j++) {
            int kcol = c0 + tx * 8 + j;
            float hv[8], lv[8];
#pragma unroll
            for (int i = 0; i < 8; i++) {
                float f = acc[i][j] + bv[j];
                hv[i] = __uint_as_float(tf32_bits(f));
                lv[i] = f - hv[i];              // exact residual
            }
            float* dh = O + (size_t)kcol * MROWS + r0 + ty * 8;
            float* dl = dh + (size_t)256 * MROWS;
            *(float4*)(dh)     = *(float4*)&hv[0];
            *(float4*)(dh + 4) = *(float4*)&hv[4];
            *(float4*)(dl)     = *(float4*)&lv[0];
            *(float4*)(dl + 4) = *(float4*)&lv[4];
        }
    }
}

// ---------------- sim GEMM: mma.sync tf32, bulk-copy pipeline ---------------
__global__ __launch_bounds__(256, 1)
void sim_mma_kernel(float* __restrict__ C)
{
    extern __shared__ __align__(128) float dsm[];
    __shared__ __align__(8) unsigned long long mbars[NSTB];
    __shared__ float wmax[8];

    const int tid = threadIdx.x;
    const int lid = tid & 31, wid = tid >> 5;
    const int warp_m = wid >> 1, warp_n = wid & 1;   // 4 x 2 warps, 64x64 each
    const int gr = lid >> 2, gc = lid & 3;
    const int m0 = blockIdx.y * TM;
    const int n0 = blockIdx.x * TN;

    uint32_t mb[NSTB];
#pragma unroll
    for (int b = 0; b < NSTB; b++)
        mb[b] = (uint32_t)__cvta_generic_to_shared(&mbars[b]);
    const uint32_t sbase = (uint32_t)__cvta_generic_to_shared(dsm);

    if (tid == 0) {
#pragma unroll
        for (int b = 0; b < NSTB; b++)
            asm volatile("mbarrier.init.shared.b64 [%0], 1;" :: "r"(mb[b]) : "memory");
    }
    __syncthreads();

    float acc[4][8][4];
#pragma unroll
    for (int i = 0; i < 4; i++)
#pragma unroll
        for (int j = 0; j < 8; j++)
#pragma unroll
            for (int q = 0; q < 4; q++) acc[i][j][q] = 0.0f;

    // stage s: term t = s/16; A k-offset (t==2?256:0)+r, B k-offset (t==1?256:0)+r
#define ISSUE(s)                                                               \
    do {                                                                       \
        int t_ = (s) >> 4;                                                     \
        int r_ = ((s) & 15) * 16;                                              \
        int ao_ = (t_ == 2 ? 256 : 0) + r_;                                    \
        int bo_ = (t_ == 1 ? 256 : 0) + r_;                                    \
        int sb_ = (s) & (NSTB - 1);                                            \
        uint32_t mbar_ = mb[sb_];                                              \
        asm volatile("mbarrier.arrive.expect_tx.shared.b64 _, [%0], %1;"       \
                     :: "r"(mbar_), "r"((uint32_t)STAGE_BYTES) : "memory");    \
        uint32_t da_ = sbase + (sb_ * A_STG) * 4;                              \
        uint32_t db_ = sbase + (B_BASE + sb_ * B_STG) * 4;                     \
        _Pragma("unroll")                                                      \
        for (int k_ = 0; k_ < 16; k_++) {                                      \
            bulk_cp(da_ + k_ * A_RSTRIDE * 4,                                  \
                    g_a2t + (size_t)(ao_ + k_) * MROWS + m0, 1024, mbar_);     \
            bulk_cp(db_ + k_ * B_RSTRIDE * 4,                                  \
                    g_b2t + (size_t)(bo_ + k_) * NCOLS + n0, 512, mbar_);      \
        }                                                                      \
    } while (0)

    if (tid == 0) { ISSUE(0); ISSUE(1); ISSUE(2); }

    uint32_t ph = 0;   // bit b = phase of buffer b
#pragma unroll 1
    for (int s = 0; s < NSTAGE; s++) {
        const int sb = s & (NSTB - 1);
        mbar_wait(mb[sb], (ph >> sb) & 1);
        ph ^= (1u << sb);

        const float* Asb = dsm + sb * A_STG;
        const float* Bsb = dsm + B_BASE + sb * B_STG;
#pragma unroll
        for (int kk = 0; kk < 16; kk += 8) {
            uint32_t a[4][4], b[8][2];
#pragma unroll
            for (int i = 0; i < 4; i++) {
                const float* p = Asb + (kk + gc) * A_RSTRIDE
                               + warp_m * 64 + i * 16 + gr;
                a[i][0] = __float_as_uint(p[0]);
                a[i][1] = __float_as_uint(p[8]);
                a[i][2] = __float_as_uint(p[4 * A_RSTRIDE]);
                a[i][3] = __float_as_uint(p[4 * A_RSTRIDE + 8]);
            }
#pragma unroll
            for (int j = 0; j < 8; j++) {
                const float* p = Bsb + (kk + gc) * B_RSTRIDE
                               + warp_n * 64 + j * 8 + gr;
                b[j][0] = __float_as_uint(p[0]);
                b[j][1] = __float_as_uint(p[4 * B_RSTRIDE]);
            }
#pragma unroll
            for (int i = 0; i < 4; i++)
#pragma unroll
                for (int j = 0; j < 8; j++) {
                    asm volatile(
                        "mma.sync.aligned.m16n8k8.row.col.f32.tf32.tf32.f32 "
                        "{%0,%1,%2,%3}, {%4,%5,%6,%7}, {%8,%9}, {%0,%1,%2,%3};"
                        : "+f"(acc[i][j][0]), "+f"(acc[i][j][1]),
                          "+f"(acc[i][j][2]), "+f"(acc[i][j][3])
                        : "r"(a[i][0]), "r"(a[i][1]), "r"(a[i][2]), "r"(a[i][3]),
                          "r"(b[j][0]), "r"(b[j][1]));
                }
        }
        __syncthreads();
        if (tid == 0 && s + 3 < NSTAGE) ISSUE(s + 3);
    }
#undef ISSUE

    // ---- epilogue: streaming stores + block max ----
    float bmax = -3.0e38f;
#pragma unroll
    for (int i = 0; i < 4; i++) {
#pragma unroll
        for (int j = 0; j < 8; j++) {
            int row = m0 + warp_m * 64 + i * 16 + gr;
            int col = n0 + warp_n * 64 + j * 8 + gc * 2;
            float* d0 = C + (size_t)row * NCOLS + col;
            float* d1 = d0 + 8 * (size_t)NCOLS;
            asm volatile("st.global.cs.v2.f32 [%0], {%1,%2};"
                         :: "l"(d0), "f"(acc[i][j][0]), "f"(acc[i][j][1]) : "memory");
            asm volatile("st.global.cs.v2.f32 [%0], {%1,%2};"
                         :: "l"(d1), "f"(acc[i][j][2]), "f"(acc[i][j][3]) : "memory");
            bmax = fmaxf(bmax, fmaxf(fmaxf(acc[i][j][0], acc[i][j][1]),
                                     fmaxf(acc[i][j][2], acc[i][j][3])));
        }
    }
#pragma unroll
    for (int o = 16; o; o >>= 1) bmax = fmaxf(bmax, __shfl_xor_sync(~0u, bmax, o));
    if (lid == 0) wmax[wid] = bmax;
    __syncthreads();
    if (tid == 0) {
        float mm = wmax[0];
#pragma unroll
        for (int i = 1; i < 8; i++) mm = fmaxf(mm, wmax[i]);
        g_blockmax[blockIdx.y * gridDim.x + blockIdx.x] = mm;
    }
}

// ---------------- threshold: radix-select over 2048 block maxima -----------
__global__ void thresh_kernel()
{
    __shared__ unsigned int cs[32];
    __shared__ unsigned int Ts;
    const int tid = threadIdx.x;  // 1024 threads
    const int w = tid >> 5, l = tid & 31;
    unsigned int k0 = fkey(g_blockmax[tid]);
    unsigned int k1 = fkey(g_blockmax[tid + 1024]);
    if (tid == 0) Ts = 0u;
    __syncthreads();
    for (int bit = 31; bit >= 8; bit--) {
        unsigned int Tc = Ts | (1u << bit);
        unsigned int c = (unsigned)(k0 >= Tc) + (unsigned)(k1 >= Tc);
#pragma unroll
        for (int o = 16; o; o >>= 1) c += __shfl_xor_sync(~0u, c, o);
        if (l == 0) cs[w] = c;
        __syncthreads();
        if (tid < 32) {
            unsigned int t = cs[tid];
#pragma unroll
            for (int o = 16; o; o >>= 1) t += __shfl_xor_sync(~0u, t, o);
            if (tid == 0 && t >= TOPK) Ts = Tc;
        }
        __syncthreads();
    }
    if (tid == 0) {
        unsigned int T = Ts;
        float f;
        if (T < 0x01000000u) f = -3.0e38f;
        else if (T & 0x80000000u) f = __uint_as_float(T ^ 0x80000000u);
        else f = __uint_as_float(~T);
        g_thresh = f - (fabsf(f) * 1e-4f + 1e-6f);   // tf32 ordering margin
        g_ccount = 0;
    }
}

// ---------------- collect candidates >= threshold ---------------------------
__device__ __forceinline__ void push_cand(float v, unsigned int idx)
{
    unsigned int pos = atomicAdd(&g_ccount, 1u);
    if (pos < CAND_BUF) {
        unsigned long long e =
            ((unsigned long long)fkey(v) << 32) | (unsigned int)(~idx);
        g_cand[pos] = e;
    }
}

__global__ void collect_kernel(const float* __restrict__ S)
{
    const float T = g_thresh;
    const size_t total4 = (size_t)MROWS * NCOLS / 4;
    const size_t stride = (size_t)gridDim.x * blockDim.x;
    for (size_t q = (size_t)blockIdx.x * blockDim.x + threadIdx.x;
         q < total4; q += stride) {
        float4 v = ((const float4*)S)[q];
        unsigned int base = (unsigned int)(q * 4);
        if (v.x >= T) push_cand(v.x, base + 0);
        if (v.y >= T) push_cand(v.y, base + 1);
        if (v.z >= T) push_cand(v.z, base + 2);
        if (v.w >= T) push_cand(v.w, base + 3);
    }
}

// ---------------- recompute candidate values exactly (fp64, warp/cand) -----
__global__ void recompute_kernel()
{
    unsigned int cnt = g_ccount;
    if (cnt > CAND_BUF) cnt = CAND_BUF;
    const int gw = (blockIdx.x * blockDim.x + threadIdx.x) >> 5;
    const int nw = (gridDim.x * blockDim.x) >> 5;
    const int lid = threadIdx.x & 31;
    for (unsigned int i = gw; i < cnt; i += nw) {
        unsigned long long e = g_cand[i];
        unsigned int idx = ~(unsigned int)(e & 0xFFFFFFFFull);
        int r = idx >> 13, c = idx & (NCOLS - 1);
        double s = 0.0;
#pragma unroll
        for (int k = 0; k < 8; k++) {
            int kk = lid + k * 32;
            double av = (double)(g_a2t[(size_t)kk * MROWS + r] +
                                 g_a2t[(size_t)(kk + 256) * MROWS + r]);
            double bv = (double)(g_b2t[(size_t)kk * NCOLS + c] +
                                 g_b2t[(size_t)(kk + 256) * NCOLS + c]);
            s = fma(av, bv, s);
        }
#pragma unroll
        for (int o = 16; o; o >>= 1) s += __shfl_down_sync(0xffffffffu, s, o);
        if (lid == 0) {
            float v = (float)s;
            g_cand[i] = ((unsigned long long)fkey(v) << 32)
                      | (unsigned long long)(e & 0xFFFFFFFFull);
        }
    }
}

// ---------------- final: sort candidates, emit (row, col) pairs ------------
__global__ void final_kernel(float* __restrict__ out)
{
    __shared__ unsigned long long s[CAND_SORT];
    __shared__ unsigned long long red[32];
    const int tid = threadIdx.x;  // 1024 threads
    unsigned int cnt = g_ccount;
    if (cnt > CAND_BUF) cnt = CAND_BUF;

    if (cnt <= CAND_SORT) {
        for (int i = tid; i < CAND_SORT; i += 1024)
            s[i] = (i < (int)cnt) ? g_cand[i] : 0ull;
        __syncthreads();
        for (int k = 2; k <= CAND_SORT; k <<= 1) {
            for (int j = k >> 1; j > 0; j >>= 1) {
                for (int i = tid; i < CAND_SORT; i += 1024) {
                    int ixj = i ^ j;
                    if (ixj > i) {
                        bool desc = ((i & k) == 0);
                        unsigned long long a = s[i], b = s[ixj];
                        if (desc ? (a < b) : (a > b)) { s[i] = b; s[ixj] = a; }
                    }
                }
                __syncthreads();
            }
        }
        for (int i = tid; i < TOPK; i += 1024) {
            unsigned int idx = ~(unsigned int)(s[i] & 0xFFFFFFFFull);
            out[2 * i + 0] = (float)(idx >> 13);
            out[2 * i + 1] = (float)(idx & (NCOLS - 1));
        }
    } else {
        for (int r = 0; r < TOPK; r++) {
            unsigned long long best = 0ull;
            for (unsigned int i = tid; i < cnt; i += 1024) {
                unsigned long long v = g_cand[i];
                if (v > best) best = v;
            }
#pragma unroll
            for (int o = 16; o; o >>= 1) {
                unsigned long long other = __shfl_down_sync(0xffffffffu, best, o);
                if (other > best) best = other;
            }
            if ((tid & 31) == 0) red[tid >> 5] = best;
            __syncthreads();
            if (tid < 32) {
                unsigned long long b = red[tid];
#pragma unroll
                for (int o = 16; o; o >>= 1) {
                    unsigned long long other = __shfl_down_sync(0xffffffffu, b, o);
                    if (other > b) b = other;
                }
                if (tid == 0) red[0] = b;
            }
            __syncthreads();
            best = red[0];
            for (unsigned int i = tid; i < cnt; i += 1024)
                if (g_cand[i] == best) g_cand[i] = 0ull;
            if (tid == 0) {
                unsigned int idx = ~(unsigned int)(best & 0xFFFFFFFFull);
                out[2 * r + 0] = (float)(idx >> 13);
                out[2 * r + 1] = (float)(idx & (NCOLS - 1));
            }
            __syncthreads();
        }
    }
}

// ---------------- launch ----------------------------------------------------
extern "C" void kernel_launch(void* const* d_in, const int* in_sizes, int n_in,
                              void* d_out, int out_size)
{
    const float* desc0 = (const float*)d_in[0];
    const float* desc1 = (const float*)d_in[1];
    const float* W0a = (const float*)d_in[2];
    const float* b0a = (const float*)d_in[3];
    const float* W0b = (const float*)d_in[4];
    const float* b0b = (const float*)d_in[5];
    const float* W1a = (const float*)d_in[6];
    const float* b1a = (const float*)d_in[7];
    const float* W1b = (const float*)d_in[8];
    const float* b1b = (const float*)d_in[9];

    float* out = (float*)d_out;
    float* sim = out + 2 * TOPK;  // indices first, then sim [8192, 8192]

    cudaFuncSetAttribute(sim_mma_kernel,
                         cudaFuncAttributeMaxDynamicSharedMemorySize, SIM_SMEM);

    dim3 mgrid(DH / BN, MROWS / BM, 2);   // (2, 64, 2)
    mlp_gemm_kernel<<<mgrid, NTHREADS>>>(desc0, desc1, W0a, W1a, b0a, b1a, 0);
    mlp_gemm_kernel<<<mgrid, NTHREADS>>>(desc0, desc1, W0b, W1b, b0b, b1b, 1);

    dim3 sgrid(NBX, NBY);                 // (64, 32)
    sim_mma_kernel<<<sgrid, 256, SIM_SMEM>>>(sim);

    thresh_kernel<<<1, 1024>>>();
    collect_kernel<<<2048, 256>>>(sim);
    recompute_kernel<<<256, 256>>>();
    final_kernel<<<1, 1024>>>(out);
}

// round 7
// speedup vs baseline: 1.7674x; 1.7674x over previous
#include <cuda_runtime.h>
#include <cuda_fp16.h>
#include <cstdint>

#define MROWS 8192
#define NCOLS 8192
#define DIN   128
#define DH    256
#define TOPK  512

// ---------- MLP tiling ----------
#define BM 128
#define BN 128
#define BK 16
#define NTHREADS 256

// ---------- sim tiling (mma.sync m16n8k16 fp16, 3-term split) ----------
#define TM 128
#define TN 128
#define KSTG 32              // k-halves per stage
#define NSTAGE 24            // 3 terms x 8 stages (K_eff = 768)
#define NBUF 4
#define SH 40                // smem halves per row (32 + 8 pad, conflict-free)
#define STG_HALVES (128 * SH)            // 5120 per matrix per stage
#define SIM_SMEM (NBUF * 2 * STG_HALVES * 2)   // 81920 B

#define NBX (NCOLS / TN)     // 64
#define NBY (MROWS / TM)     // 64
#define NBLOCKS (NBX * NBY)  // 4096

#define CAND_BUF  32768
#define CAND_SORT 4096

// ---------------- scratch (device globals; no allocation allowed) ----------
__device__ __align__(128) float g_hid0[MROWS * DH];
__device__ __align__(128) float g_hid1[NCOLS * DH];
__device__ __align__(128) float g_md0[MROWS * DH];    // exact fp32 (recompute)
__device__ __align__(128) float g_md1[NCOLS * DH];
__device__ __align__(128) __half g_ah[MROWS * DH];    // fp16 hi
__device__ __align__(128) __half g_al[MROWS * DH];    // fp16 lo
__device__ __align__(128) __half g_bh[NCOLS * DH];
__device__ __align__(128) __half g_bl[NCOLS * DH];
__device__ float g_blockmax[NBLOCKS];
__device__ float g_thresh;
__device__ unsigned int g_ccount;
__device__ unsigned long long g_cand[CAND_BUF];

// monotone float -> uint key
__device__ __forceinline__ unsigned int fkey(float f) {
    unsigned int u = __float_as_uint(f);
    return (u & 0x80000000u) ? ~u : (u | 0x80000000u);
}

__device__ __forceinline__ void cp16(uint32_t smem_dst, const void* src) {
    asm volatile("cp.async.cg.shared.global [%0], [%1], 16;"
                 :: "r"(smem_dst), "l"(src) : "memory");
}

// ---------------- MLP GEMM: O = act(A @ W + b), N = DH = 256 ---------------
__global__ __launch_bounds__(NTHREADS, 2)
void mlp_gemm_kernel(const float* __restrict__ in0, const float* __restrict__ in1,
                     const float* __restrict__ Wd0, const float* __restrict__ Wd1,
                     const float* __restrict__ bd0, const float* __restrict__ bd1,
                     int layer)
{
    const int z = blockIdx.z;
    const float* A;
    int K, relu;
    float* Omd;
    __half *Oh, *Ol;
    if (layer == 0) {
        A = z ? in1 : in0;
        Omd = z ? g_hid1 : g_hid0;
        Oh = 0; Ol = 0;
        K = DIN; relu = 1;
    } else {
        A = z ? g_hid1 : g_hid0;
        Omd = z ? g_md1 : g_md0;
        Oh = z ? g_bh : g_ah;
        Ol = z ? g_bl : g_al;
        K = DH; relu = 0;
    }
    const float* W = z ? Wd1 : Wd0;
    const float* bias = z ? bd1 : bd0;

    __shared__ float As[BK][BM];
    __shared__ float Bs[BK][BN];

    const int tid = threadIdx.x;
    const int tx = tid & 15, ty = tid >> 4;
    const int r0 = blockIdx.y * BM;
    const int c0 = blockIdx.x * BN;

    float acc[8][8];
#pragma unroll
    for (int i = 0; i < 8; i++)
#pragma unroll
        for (int j = 0; j < 8; j++) acc[i][j] = 0.0f;

    for (int k0 = 0; k0 < K; k0 += BK) {
#pragma unroll
        for (int i = 0; i < 2; i++) {
            int f = tid * 2 + i;
            int row = f >> 2;
            int kq = (f & 3) << 2;
            float4 v = *(const float4*)(A + (size_t)(r0 + row) * K + k0 + kq);
            As[kq + 0][row] = v.x; As[kq + 1][row] = v.y;
            As[kq + 2][row] = v.z; As[kq + 3][row] = v.w;
        }
#pragma unroll
        for (int i = 0; i < 2; i++) {
            int f = tid * 2 + i;
            int kk = f >> 5;
            int nq = (f & 31) << 2;
            *(float4*)&Bs[kk][nq] =
                *(const float4*)(W + (size_t)(k0 + kk) * DH + c0 + nq);
        }
        __syncthreads();
#pragma unroll
        for (int kk = 0; kk < BK; kk++) {
            float a[8], b[8];
            *(float4*)&a[0] = *(float4*)&As[kk][ty * 8];
            *(float4*)&a[4] = *(float4*)&As[kk][ty * 8 + 4];
            *(float4*)&b[0] = *(float4*)&Bs[kk][tx * 8];
            *(float4*)&b[4] = *(float4*)&Bs[kk][tx * 8 + 4];
#pragma unroll
            for (int i = 0; i < 8; i++)
#pragma unroll
                for (int j = 0; j < 8; j++)
                    acc[i][j] = fmaf(a[i], b[j], acc[i][j]);
        }
        __syncthreads();
    }

    float bv[8];
    *(float4*)&bv[0] = *(const float4*)(bias + c0 + tx * 8);
    *(float4*)&bv[4] = *(const float4*)(bias + c0 + tx * 8 + 4);

#pragma unroll
    for (int i = 0; i < 8; i++) {
        int row = r0 + ty * 8 + i;
        float f[8];
#pragma unroll
        for (int j = 0; j < 8; j++) f[j] = acc[i][j] + bv[j];
        if (relu) {
#pragma unroll
            for (int j = 0; j < 8; j++) f[j] = fmaxf(f[j], 0.0f);
            *(float4*)(Omd + (size_t)row * DH + c0 + tx * 8) = *(float4*)&f[0];
            *(float4*)(Omd + (size_t)row * DH + c0 + tx * 8 + 4) = *(float4*)&f[4];
        } else {
            __half hh[8], ll[8];
#pragma unroll
            for (int j = 0; j < 8; j++) {
                __half h = __float2half_rn(f[j]);
                hh[j] = h;
                ll[j] = __float2half_rn(f[j] - __half2float(h));
            }
            size_t off = (size_t)row * DH + c0 + tx * 8;
            *(float4*)(Omd + off)     = *(float4*)&f[0];
            *(float4*)(Omd + off + 4) = *(float4*)&f[4];
            *(uint4*)(Oh + off) = *(uint4*)hh;
            *(uint4*)(Ol + off) = *(uint4*)ll;
        }
    }
}

// ---------------- no-op (aligns ncu -s 5 capture onto sim kernel) ----------
__global__ void noop_kernel() {}

// ---------------- sim GEMM: fp16 m16n8k16, 3-term hi/lo --------------------
__global__ __launch_bounds__(256, 2)
void sim_mma_kernel(float* __restrict__ C)
{
    extern __shared__ __align__(128) __half hsm[];
    __shared__ float wmax[8];

    const int tid = threadIdx.x;
    const int lid = tid & 31, wid = tid >> 5;
    const int warp_m = wid >> 2, warp_n = wid & 3;   // 2 x 4 warps, 64x32
    const int gr = lid >> 2, gc = lid & 3;
    const int m0 = blockIdx.y * TM;
    const int n0 = blockIdx.x * TN;

    const uint32_t sbase = (uint32_t)__cvta_generic_to_shared(hsm);
    const int ld_row = tid >> 1;          // 2 threads per row
    const int ld_q   = (tid & 1) * 2;     // each thread: quads q, q+1 (16B each)

    float acc[4][4][4];
#pragma unroll
    for (int i = 0; i < 4; i++)
#pragma unroll
        for (int j = 0; j < 4; j++)
#pragma unroll
            for (int q = 0; q < 4; q++) acc[i][j][q] = 0.0f;

    // stage s: term t=s/8, k-offset r=(s%8)*32
    // A uses lo iff t==2, B uses lo iff t==1
#define ISSUE(s)                                                               \
    do {                                                                       \
        int t_ = (s) >> 3;                                                     \
        int r_ = ((s) & 7) * KSTG;                                             \
        const __half* ga_ = (t_ == 2 ? g_al : g_ah) + (size_t)(m0 + ld_row) * DH + r_; \
        const __half* gb_ = (t_ == 1 ? g_bl : g_bh) + (size_t)(n0 + ld_row) * DH + r_; \
        int bf_ = (s) & (NBUF - 1);                                            \
        uint32_t da_ = sbase + (bf_ * STG_HALVES + ld_row * SH) * 2;           \
        uint32_t db_ = da_ + NBUF * STG_HALVES * 2;                            \
        cp16(da_ + ld_q * 16, ga_ + ld_q * 8);                                 \
        cp16(da_ + ld_q * 16 + 16, ga_ + ld_q * 8 + 8);                        \
        cp16(db_ + ld_q * 16, gb_ + ld_q * 8);                                 \
        cp16(db_ + ld_q * 16 + 16, gb_ + ld_q * 8 + 8);                        \
        asm volatile("cp.async.commit_group;" ::: "memory");                   \
    } while (0)

    ISSUE(0); ISSUE(1); ISSUE(2);

#pragma unroll 1
    for (int s = 0; s < NSTAGE; s++) {
        if (s <= NSTAGE - 3)
            asm volatile("cp.async.wait_group 2;" ::: "memory");
        else if (s == NSTAGE - 2)
            asm volatile("cp.async.wait_group 1;" ::: "memory");
        else
            asm volatile("cp.async.wait_group 0;" ::: "memory");
        __syncthreads();
        if (s + 3 < NSTAGE) ISSUE(s + 3);

        const __half* Ab = hsm + (s & (NBUF - 1)) * STG_HALVES;
        const __half* Bb = Ab + NBUF * STG_HALVES;
#pragma unroll
        for (int kk = 0; kk < KSTG; kk += 16) {
            uint32_t a[4][4], b[4][2];
#pragma unroll
            for (int i = 0; i < 4; i++) {
                const __half* p = Ab + (warp_m * 64 + i * 16 + gr) * SH + kk + 2 * gc;
                a[i][0] = *(const uint32_t*)(p);
                a[i][1] = *(const uint32_t*)(p + 8 * SH);
                a[i][2] = *(const uint32_t*)(p + 8);
                a[i][3] = *(const uint32_t*)(p + 8 * SH + 8);
            }
#pragma unroll
            for (int j = 0; j < 4; j++) {
                const __half* p = Bb + (warp_n * 32 + j * 8 + gr) * SH + kk + 2 * gc;
                b[j][0] = *(const uint32_t*)(p);
                b[j][1] = *(const uint32_t*)(p + 8);
            }
#pragma unroll
            for (int i = 0; i < 4; i++)
#pragma unroll
                for (int j = 0; j < 4; j++) {
                    asm volatile(
                        "mma.sync.aligned.m16n8k16.row.col.f32.f16.f16.f32 "
                        "{%0,%1,%2,%3}, {%4,%5,%6,%7}, {%8,%9}, {%0,%1,%2,%3};"
                        : "+f"(acc[i][j][0]), "+f"(acc[i][j][1]),
                          "+f"(acc[i][j][2]), "+f"(acc[i][j][3])
                        : "r"(a[i][0]), "r"(a[i][1]), "r"(a[i][2]), "r"(a[i][3]),
                          "r"(b[j][0]), "r"(b[j][1]));
                }
        }
        __syncthreads();
    }
#undef ISSUE

    // ---- epilogue: streaming stores + block max ----
    float bmax = -3.0e38f;
#pragma unroll
    for (int i = 0; i < 4; i++) {
#pragma unroll
        for (int j = 0; j < 4; j++) {
            int row = m0 + warp_m * 64 + i * 16 + gr;
            int col = n0 + warp_n * 32 + j * 8 + gc * 2;
            float* d0 = C + (size_t)row * NCOLS + col;
            float* d1 = d0 + 8 * (size_t)NCOLS;
            asm volatile("st.global.cs.v2.f32 [%0], {%1,%2};"
                         :: "l"(d0), "f"(acc[i][j][0]), "f"(acc[i][j][1]) : "memory");
            asm volatile("st.global.cs.v2.f32 [%0], {%1,%2};"
                         :: "l"(d1), "f"(acc[i][j][2]), "f"(acc[i][j][3]) : "memory");
            bmax = fmaxf(bmax, fmaxf(fmaxf(acc[i][j][0], acc[i][j][1]),
                                     fmaxf(acc[i][j][2], acc[i][j][3])));
        }
    }
#pragma unroll
    for (int o = 16; o; o >>= 1) bmax = fmaxf(bmax, __shfl_xor_sync(~0u, bmax, o));
    if (lid == 0) wmax[wid] = bmax;
    __syncthreads();
    if (tid == 0) {
        float mm = wmax[0];
#pragma unroll
        for (int i = 1; i < 8; i++) mm = fmaxf(mm, wmax[i]);
        g_blockmax[blockIdx.y * gridDim.x + blockIdx.x] = mm;
    }
}

// ---------------- threshold: radix-select over 4096 block maxima -----------
__global__ void thresh_kernel()
{
    __shared__ unsigned int cs[32];
    __shared__ unsigned int Ts;
    const int tid = threadIdx.x;  // 1024 threads
    const int w = tid >> 5, l = tid & 31;
    unsigned int k[4];
#pragma unroll
    for (int q = 0; q < 4; q++) k[q] = fkey(g_blockmax[tid + q * 1024]);
    if (tid == 0) Ts = 0u;
    __syncthreads();
    for (int bit = 31; bit >= 8; bit--) {
        unsigned int Tc = Ts | (1u << bit);
        unsigned int c = 0;
#pragma unroll
        for (int q = 0; q < 4; q++) c += (unsigned)(k[q] >= Tc);
#pragma unroll
        for (int o = 16; o; o >>= 1) c += __shfl_xor_sync(~0u, c, o);
        if (l == 0) cs[w] = c;
        __syncthreads();
        if (tid < 32) {
            unsigned int t = cs[tid];
#pragma unroll
            for (int o = 16; o; o >>= 1) t += __shfl_xor_sync(~0u, t, o);
            if (tid == 0 && t >= TOPK) Ts = Tc;
        }
        __syncthreads();
    }
    if (tid == 0) {
        unsigned int T = Ts;
        float f;
        if (T < 0x01000000u) f = -3.0e38f;
        else if (T & 0x80000000u) f = __uint_as_float(T ^ 0x80000000u);
        else f = __uint_as_float(~T);
        g_thresh = f - (fabsf(f) * 1e-4f + 1e-6f);   // fp16-split ordering margin
        g_ccount = 0;
    }
}

// ---------------- collect candidates >= threshold ---------------------------
__device__ __forceinline__ void push_cand(float v, unsigned int idx)
{
    unsigned int pos = atomicAdd(&g_ccount, 1u);
    if (pos < CAND_BUF) {
        unsigned long long e =
            ((unsigned long long)fkey(v) << 32) | (unsigned int)(~idx);
        g_cand[pos] = e;
    }
}

__global__ void collect_kernel(const float* __restrict__ S)
{
    const float T = g_thresh;
    const size_t total4 = (size_t)MROWS * NCOLS / 4;
    const size_t stride = (size_t)gridDim.x * blockDim.x;
    for (size_t q = (size_t)blockIdx.x * blockDim.x + threadIdx.x;
         q < total4; q += stride) {
        float4 v = ((const float4*)S)[q];
        unsigned int base = (unsigned int)(q * 4);
        if (v.x >= T) push_cand(v.x, base + 0);
        if (v.y >= T) push_cand(v.y, base + 1);
        if (v.z >= T) push_cand(v.z, base + 2);
        if (v.w >= T) push_cand(v.w, base + 3);
    }
}

// ---------------- recompute candidate values exactly (fp64, warp/cand) -----
__global__ void recompute_kernel()
{
    unsigned int cnt = g_ccount;
    if (cnt > CAND_BUF) cnt = CAND_BUF;
    const int gw = (blockIdx.x * blockDim.x + threadIdx.x) >> 5;
    const int nw = (gridDim.x * blockDim.x) >> 5;
    const int lid = threadIdx.x & 31;
    for (unsigned int i = gw; i < cnt; i += nw) {
        unsigned long long e = g_cand[i];
        unsigned int idx = ~(unsigned int)(e & 0xFFFFFFFFull);
        int r = idx >> 13, c = idx & (NCOLS - 1);
        const float* ar = g_md0 + (size_t)r * DH;
        const float* br = g_md1 + (size_t)c * DH;
        double s = 0.0;
#pragma unroll
        for (int k = 0; k < 8; k++) {
            int kk = lid + k * 32;
            s = fma((double)ar[kk], (double)br[kk], s);
        }
#pragma unroll
        for (int o = 16; o; o >>= 1) s += __shfl_down_sync(0xffffffffu, s, o);
        if (lid == 0) {
            float v = (float)s;
            g_cand[i] = ((unsigned long long)fkey(v) << 32)
                      | (unsigned long long)(e & 0xFFFFFFFFull);
        }
    }
}

// ---------------- final: sort candidates, emit (row, col) pairs ------------
__global__ void final_kernel(float* __restrict__ out)
{
    __shared__ unsigned long long s[CAND_SORT];
    __shared__ unsigned long long red[32];
    const int tid = threadIdx.x;  // 1024 threads
    unsigned int cnt = g_ccount;
    if (cnt > CAND_BUF) cnt = CAND_BUF;

    if (cnt <= CAND_SORT) {
        for (int i = tid; i < CAND_SORT; i += 1024)
            s[i] = (i < (int)cnt) ? g_cand[i] : 0ull;
        __syncthreads();
        for (int k = 2; k <= CAND_SORT; k <<= 1) {
            for (int j = k >> 1; j > 0; j >>= 1) {
                for (int i = tid; i < CAND_SORT; i += 1024) {
                    int ixj = i ^ j;
                    if (ixj > i) {
                        bool desc = ((i & k) == 0);
                        unsigned long long a = s[i], b = s[ixj];
                        if (desc ? (a < b) : (a > b)) { s[i] = b; s[ixj] = a; }
                    }
                }
                __syncthreads();
            }
        }
        for (int i = tid; i < TOPK; i += 1024) {
            unsigned int idx = ~(unsigned int)(s[i] & 0xFFFFFFFFull);
            out[2 * i + 0] = (float)(idx >> 13);
            out[2 * i + 1] = (float)(idx & (NCOLS - 1));
        }
    } else {
        for (int r = 0; r < TOPK; r++) {
            unsigned long long best = 0ull;
            for (unsigned int i = tid; i < cnt; i += 1024) {
                unsigned long long v = g_cand[i];
                if (v > best) best = v;
            }
#pragma unroll
            for (int o = 16; o; o >>= 1) {
                unsigned long long other = __shfl_down_sync(0xffffffffu, best, o);
                if (other > best) best = other;
            }
            if ((tid & 31) == 0) red[tid >> 5] = best;
            __syncthreads();
            if (tid < 32) {
                unsigned long long b = red[tid];
#pragma unroll
                for (int o = 16; o; o >>= 1) {
                    unsigned long long other = __shfl_down_sync(0xffffffffu, b, o);
                    if (other > b) b = other;
                }
                if (tid == 0) red[0] = b;
            }
            __syncthreads();
            best = red[0];
            for (unsigned int i = tid; i < cnt; i += 1024)
                if (g_cand[i] == best) g_cand[i] = 0ull;
            if (tid == 0) {
                unsigned int idx = ~(unsigned int)(best & 0xFFFFFFFFull);
                out[2 * r + 0] = (float)(idx >> 13);
                out[2 * r + 1] = (float)(idx & (NCOLS - 1));
            }
            __syncthreads();
        }
    }
}

// ---------------- launch ----------------------------------------------------
extern "C" void kernel_launch(void* const* d_in, const int* in_sizes, int n_in,
                              void* d_out, int out_size)
{
    const float* desc0 = (const float*)d_in[0];
    const float* desc1 = (const float*)d_in[1];
    const float* W0a = (const float*)d_in[2];
    const float* b0a = (const float*)d_in[3];
    const float* W0b = (const float*)d_in[4];
    const float* b0b = (const float*)d_in[5];
    const float* W1a = (const float*)d_in[6];
    const float* b1a = (const float*)d_in[7];
    const float* W1b = (const float*)d_in[8];
    const float* b1b = (const float*)d_in[9];

    float* out = (float*)d_out;
    float* sim = out + 2 * TOPK;  // indices first, then sim [8192, 8192]

    cudaFuncSetAttribute(sim_mma_kernel,
                         cudaFuncAttributeMaxDynamicSharedMemorySize, SIM_SMEM);

    dim3 mgrid(DH / BN, MROWS / BM, 2);   // (2, 64, 2)
    mlp_gemm_kernel<<<mgrid, NTHREADS>>>(desc0, desc1, W0a, W1a, b0a, b1a, 0);
    mlp_gemm_kernel<<<mgrid, NTHREADS>>>(desc0, desc1, W0b, W1b, b0b, b1b, 1);

    noop_kernel<<<1, 32>>>();             // ncu -s 5 alignment: sim is launch #4

    dim3 sgrid(NBX, NBY);                 // (64, 64)
    sim_mma_kernel<<<sgrid, 256, SIM_SMEM>>>(sim);

    thresh_kernel<<<1, 1024>>>();
    collect_kernel<<<2048, 256>>>(sim);
    recompute_kernel<<<256, 256>>>();
    final_kernel<<<1, 1024>>>(out);
}